// round 16
// baseline (speedup 1.0000x reference)
#include <cuda_runtime.h>
#include <cuda_fp16.h>
#include <stdint.h>
#include <math.h>

// Problem constants (fixed shapes for this dataset)
#define NN 50000
#define EE 800000
#define BB 128
#define IN_DIM 310
#define KP0 320      // IN_DIM padded to multiple of 32
#define HD 128       // 2 heads x 64
#define NH 2

// ---------------- scratch (static device globals; no allocation) ----------------
__device__ __align__(16) __half g_xwh[NN * HD];      // GEMM output fp16 (for gather)
__device__ __align__(16) float g_h[NN * HD];         // aggregated layer output
__device__ __align__(8) float g_asrc[NN * NH];
__device__ __align__(8) float g_adst[NN * NH];
__device__ int   g_deg[NN];
__device__ int   g_cursor[NN];
__device__ int   g_rowptr[NN + 1];
__device__ int   g_csrsrc[EE];
__device__ int   g_root[BB + 1];

__device__ __forceinline__ float lrelu(float z) { return z > 0.f ? z : 0.2f * z; }

// ---------------- CSR build ----------------
__global__ void count_kernel(const int* __restrict__ dst) {
    int i = blockIdx.x * blockDim.x + threadIdx.x;
    if (i < EE / 4) {
        int4 d = reinterpret_cast<const int4*>(dst)[i];
        atomicAdd(&g_deg[d.x], 1);
        atomicAdd(&g_deg[d.y], 1);
        atomicAdd(&g_deg[d.z], 1);
        atomicAdd(&g_deg[d.w], 1);
    }
}

// chunked scan (1024 threads, contiguous chunks) + fused roots binary search
__global__ void scan_kernel(const int* __restrict__ batch) {
    const int CH = (NN + 1023) / 1024;     // 49
    __shared__ int ws[32];
    int t = threadIdx.x, lane = t & 31, wid = t >> 5;

    if (t <= BB) {
        if (t == BB) g_root[BB] = NN;
        else {
            int lo = 0, hi = NN;
            while (lo < hi) {
                int mid = (lo + hi) >> 1;
                if (batch[mid] < t) lo = mid + 1; else hi = mid;
            }
            g_root[t] = lo;
        }
    }

    int lo = t * CH, hi = min(lo + CH, NN);
    if (lo > NN) lo = NN;
    if (hi < lo) hi = lo;
    int sum = 0;
    for (int i = lo; i < hi; i++) sum += g_deg[i];
    int x = sum;
    #pragma unroll
    for (int o = 1; o < 32; o <<= 1) {
        int y = __shfl_up_sync(0xffffffffu, x, o);
        if (lane >= o) x += y;
    }
    if (lane == 31) ws[wid] = x;
    __syncthreads();
    if (wid == 0) {
        int w = ws[lane];
        #pragma unroll
        for (int o = 1; o < 32; o <<= 1) {
            int y = __shfl_up_sync(0xffffffffu, w, o);
            if (lane >= o) w += y;
        }
        ws[lane] = w;
    }
    __syncthreads();
    int run = x - sum + (wid ? ws[wid - 1] : 0);
    for (int i = lo; i < hi; i++) { g_rowptr[i] = run; run += g_deg[i]; }
    if (t == 1023) g_rowptr[NN] = run;
}

__global__ void fill_kernel(const int* __restrict__ src, const int* __restrict__ dst) {
    int i = blockIdx.x * blockDim.x + threadIdx.x;
    if (i < EE / 4) {
        int4 s4 = reinterpret_cast<const int4*>(src)[i];
        int4 d4 = reinterpret_cast<const int4*>(dst)[i];
        int p0 = g_rowptr[d4.x] + atomicAdd(&g_cursor[d4.x], 1);
        int p1 = g_rowptr[d4.y] + atomicAdd(&g_cursor[d4.y], 1);
        int p2 = g_rowptr[d4.z] + atomicAdd(&g_cursor[d4.z], 1);
        int p3 = g_rowptr[d4.w] + atomicAdd(&g_cursor[d4.w], 1);
        g_csrsrc[p0] = s4.x;
        g_csrsrc[p1] = s4.y;
        g_csrsrc[p2] = s4.z;
        g_csrsrc[p3] = s4.w;
    }
}

// ---------------- tf32 tensor-core GEMM: 64x128 block tile, 8 warps, no cvts ----
// Raw fp32 feeds tf32 HMMA (HW mantissa truncation, ~2^-11/elem; verified 1.8e-4
// at the output vs 1e-3 threshold). Small tile => ~90 regs & 53KB smem => 2 CTAs
// per SM for cross-CTA latency hiding (the R15 profile showed occ=12.5% binding).
#define MMA_TF32(Cr, a0, a1, a2, a3, b0, b1) \
    asm volatile("mma.sync.aligned.m16n8k8.row.col.f32.tf32.tf32.f32 " \
        "{%0,%1,%2,%3},{%4,%5,%6,%7},{%8,%9},{%0,%1,%2,%3};" \
        : "+f"((Cr)[0]), "+f"((Cr)[1]), "+f"((Cr)[2]), "+f"((Cr)[3]) \
        : "r"(a0), "r"(a1), "r"(a2), "r"(a3), "r"(b0), "r"(b1))
#define CP8(dst, src, bytes) \
    asm volatile("cp.async.ca.shared.global [%0], [%1], 8, %2;" \
        :: "r"(dst), "l"(src), "r"(bytes))
#define CP16P(dst, src, bytes) \
    asm volatile("cp.async.cg.shared.global [%0], [%1], 16, %2;" \
        :: "r"(dst), "l"(src), "r"(bytes))
#define CP_COMMIT() asm volatile("cp.async.commit_group;")
#define CP_WAIT(n)  asm volatile("cp.async.wait_group %0;" :: "n"(n))

#define BM 64
#define SA_STRIDE 36
#define SB_STRIDE 136
#define SA_ELEMS (BM * SA_STRIDE)
#define SB_ELEMS (32 * SB_STRIDE)
#define GEMM_SMEM_BYTES ((2 * SA_ELEMS + 2 * SB_ELEMS) * 4)

__global__ __launch_bounds__(256) void gemm_tf32(
    const float* __restrict__ A, const float* __restrict__ Bg,
    __half* __restrict__ Ch,
    const float* __restrict__ aS, const float* __restrict__ aD,
    int M, int K, int Kp)
{
    extern __shared__ float smem[];
    float* sA = smem;                       // [2][64][36]
    float* sB = smem + 2 * SA_ELEMS;        // [2][32][136]
    __shared__ float2 sal[BM][4];           // per-(row, wn) (asrc, adst) partials

    int tid = threadIdx.x;
    int lane = tid & 31, warp = tid >> 5;
    int wm = warp >> 2, wn = warp & 3;   // 2 x 4 warps; warp tile 32 x 32
    int row0 = blockIdx.x * BM;
    int gq = lane >> 2, tq = lane & 3;

    float acc[2][4][4];
    #pragma unroll
    for (int a = 0; a < 2; a++)
        #pragma unroll
        for (int b = 0; b < 4; b++)
            #pragma unroll
            for (int c = 0; c < 4; c++) acc[a][b][c] = 0.f;

    unsigned sA_base = (unsigned)__cvta_generic_to_shared(sA);
    unsigned sB_base = (unsigned)__cvta_generic_to_shared(sB);
    int T = Kp / 32;

    auto issue = [&](int t, int buf) {
        int kt = t * 32;
        // A: 64x32 floats = 1024 8B-chunks; thread gets 4
        #pragma unroll
        for (int q = 0; q < 4; q++) {
            int ch = tid * 4 + q;
            int r = ch >> 4, c2 = (ch & 15) * 2;
            int gm = row0 + r, gk = kt + c2;
            int bytes = 0;
            if (gm < M) {
                int rem = (K - gk) * 4;
                bytes = rem >= 8 ? 8 : (rem > 0 ? rem : 0);
            }
            unsigned ds = sA_base + (unsigned)((buf * SA_ELEMS + r * SA_STRIDE + c2) * 4);
            const float* srcp = A + (long)gm * K + gk;
            CP8(ds, srcp, bytes);
        }
        // B: 32x128 floats = 1024 16B-chunks; thread gets 4 (zero-fill past K)
        #pragma unroll
        for (int q = 0; q < 4; q++) {
            int ch = tid * 4 + q;
            int r = ch >> 5, c4 = (ch & 31) * 4;
            int bytes = (kt + r < K) ? 16 : 0;
            unsigned ds = sB_base + (unsigned)((buf * SB_ELEMS + r * SB_STRIDE + c4) * 4);
            const float* srcp = Bg + (long)(kt + r) * 128 + c4;
            CP16P(ds, srcp, bytes);
        }
    };

    issue(0, 0);
    CP_COMMIT();

    for (int t = 0; t < T; t++) {
        int buf = t & 1;
        if (t + 1 < T) {
            issue(t + 1, (t + 1) & 1);
            CP_COMMIT();
            CP_WAIT(1);
        } else {
            CP_WAIT(0);
        }
        __syncthreads();

        const float* cA = sA + buf * SA_ELEMS;
        const float* cB = sB + buf * SB_ELEMS;
        #pragma unroll
        for (int ks = 0; ks < 4; ks++) {
            int c0 = ks * 8 + tq;
            unsigned int af[2][4];
            #pragma unroll
            for (int mi = 0; mi < 2; mi++) {
                int r = wm * 32 + mi * 16 + gq;
                af[mi][0] = __float_as_uint(cA[r * SA_STRIDE + c0]);
                af[mi][1] = __float_as_uint(cA[(r + 8) * SA_STRIDE + c0]);
                af[mi][2] = __float_as_uint(cA[r * SA_STRIDE + c0 + 4]);
                af[mi][3] = __float_as_uint(cA[(r + 8) * SA_STRIDE + c0 + 4]);
            }
            unsigned int bf[4][2];
            #pragma unroll
            for (int nb = 0; nb < 4; nb++) {
                int n = wn * 32 + nb * 8 + gq;
                bf[nb][0] = __float_as_uint(cB[(ks * 8 + tq) * SB_STRIDE + n]);
                bf[nb][1] = __float_as_uint(cB[(ks * 8 + 4 + tq) * SB_STRIDE + n]);
            }
            #pragma unroll
            for (int mi = 0; mi < 2; mi++)
                #pragma unroll
                for (int nb = 0; nb < 4; nb++)
                    MMA_TF32(acc[mi][nb], af[mi][0], af[mi][1], af[mi][2], af[mi][3],
                             bf[nb][0], bf[nb][1]);
        }
        __syncthreads();
    }

    // epilogue: fp16 store + alpha partials (shfl-reduced over tq, smem-combined)
    #pragma unroll
    for (int mi = 0; mi < 2; mi++) {
        int rb = row0 + wm * 32 + mi * 16 + gq;
        float s_lo = 0.f, s_hi = 0.f, d_lo = 0.f, d_hi = 0.f;
        #pragma unroll
        for (int nb = 0; nb < 4; nb++) {
            int cc = wn * 32 + nb * 8 + tq * 2;
            float as0 = aS[cc], as1 = aS[cc + 1];
            float ad0 = aD[cc], ad1 = aD[cc + 1];
            s_lo += acc[mi][nb][0] * as0 + acc[mi][nb][1] * as1;
            d_lo += acc[mi][nb][0] * ad0 + acc[mi][nb][1] * ad1;
            s_hi += acc[mi][nb][2] * as0 + acc[mi][nb][3] * as1;
            d_hi += acc[mi][nb][2] * ad0 + acc[mi][nb][3] * ad1;
            if (rb < M)
                *reinterpret_cast<__half2*>(&Ch[(long)rb * 128 + cc]) =
                    __floats2half2_rn(acc[mi][nb][0], acc[mi][nb][1]);
            if (rb + 8 < M)
                *reinterpret_cast<__half2*>(&Ch[(long)(rb + 8) * 128 + cc]) =
                    __floats2half2_rn(acc[mi][nb][2], acc[mi][nb][3]);
        }
        #pragma unroll
        for (int o = 1; o < 4; o <<= 1) {
            s_lo += __shfl_down_sync(0xffffffffu, s_lo, o, 4);
            d_lo += __shfl_down_sync(0xffffffffu, d_lo, o, 4);
            s_hi += __shfl_down_sync(0xffffffffu, s_hi, o, 4);
            d_hi += __shfl_down_sync(0xffffffffu, d_hi, o, 4);
        }
        if (tq == 0) {
            int rl = wm * 32 + mi * 16 + gq;
            sal[rl][wn] = make_float2(s_lo, d_lo);
            sal[rl + 8][wn] = make_float2(s_hi, d_hi);
        }
    }
    __syncthreads();
    // final combine: threads 0..127 -> (row = t>>1, head = t&1)
    if (tid < 2 * BM) {
        int row = tid >> 1, head = tid & 1;
        float2 a = sal[row][2 * head];
        float2 b = sal[row][2 * head + 1];
        int gr = row0 + row;
        if (gr < M) {
            g_asrc[2 * gr + head] = a.x + b.x;
            g_adst[2 * gr + head] = a.y + b.y;
        }
    }
}

// ---------------- GAT aggregation: warp per dst node, SINGLE PASS ----------------
__global__ void aggregate_kernel(const __half* __restrict__ xh,
                                 const float* __restrict__ bias,
                                 float* __restrict__ out) {
    int gw = (blockIdx.x * blockDim.x + threadIdx.x) >> 5;
    int lane = threadIdx.x & 31;
    if (gw >= NN) return;
    int i = gw;
    int head = lane >> 4;
    float2 adp = *reinterpret_cast<const float2*>(&g_adst[2 * i]);
    float2 asp = *reinterpret_cast<const float2*>(&g_asrc[2 * i]);
    float ad0 = adp.x, ad1 = adp.y;
    float eSelf = head ? lrelu(asp.y + ad1) : lrelu(asp.x + ad0);
    int r0 = g_rowptr[i], r1 = g_rowptr[i + 1];

    float wself = __expf(eSelf);
    float den = wself;
    float4 acc;
    {
        uint2 raw = *reinterpret_cast<const uint2*>(&xh[(long)i * HD + lane * 4]);
        __half2 p0 = *reinterpret_cast<__half2*>(&raw.x);
        __half2 p1 = *reinterpret_cast<__half2*>(&raw.y);
        float2 f0 = __half22float2(p0);
        float2 f1 = __half22float2(p1);
        acc = make_float4(wself * f0.x, wself * f0.y, wself * f1.x, wself * f1.y);
    }

    for (int jb = r0; jb < r1; jb += 32) {
        int j = jb + lane;
        int s = 0; unsigned epk = 0;
        if (j < r1) {
            s = g_csrsrc[j];
            float2 a = *reinterpret_cast<const float2*>(&g_asrc[2 * s]);
            __half2 eh = __floats2half2_rn(lrelu(a.x + ad0), lrelu(a.y + ad1));
            epk = *reinterpret_cast<unsigned*>(&eh);
        }
        int cnt = min(32, r1 - jb);
        for (int k = 0; k < cnt; k++) {
            int      sk = __shfl_sync(0xffffffffu, s, k);
            unsigned ek = __shfl_sync(0xffffffffu, epk, k);
            __half2 ev = *reinterpret_cast<__half2*>(&ek);
            float e = head ? __high2float(ev) : __low2float(ev);
            float w = __expf(e);
            den += w;
            uint2 raw = *reinterpret_cast<const uint2*>(&xh[(long)sk * HD + lane * 4]);
            __half2 p0 = *reinterpret_cast<__half2*>(&raw.x);
            __half2 p1 = *reinterpret_cast<__half2*>(&raw.y);
            float2 f0 = __half22float2(p0);
            float2 f1 = __half22float2(p1);
            acc.x = fmaf(w, f0.x, acc.x);
            acc.y = fmaf(w, f0.y, acc.y);
            acc.z = fmaf(w, f1.x, acc.z);
            acc.w = fmaf(w, f1.y, acc.w);
        }
    }

    float inv = 1.f / (den + 1e-16f);
    float4 b = *reinterpret_cast<const float4*>(&bias[lane * 4]);
    float4 o;
    o.x = fmaxf(fmaf(acc.x, inv, b.x), 0.f);
    o.y = fmaxf(fmaf(acc.y, inv, b.y), 0.f);
    o.z = fmaxf(fmaf(acc.z, inv, b.z), 0.f);
    o.w = fmaxf(fmaf(acc.w, inv, b.w), 0.f);
    *reinterpret_cast<float4*>(&out[i * HD + lane * 4]) = o;
}

// ---------------- fused mean-pool + readout + news + concat + sigmoid ----------------
__global__ __launch_bounds__(512) void pool_head_kernel(
    const float* __restrict__ h, const float* __restrict__ x,
    const float* __restrict__ Wr, const float* __restrict__ br,
    const float* __restrict__ Wn, const float* __restrict__ bn,
    const float* __restrict__ Wc, const float* __restrict__ bc,
    float* __restrict__ out) {
    int b = blockIdx.x;
    int t = threadIdx.x;                    // 512
    int tt = t & 127, part = t >> 7;
    __shared__ float ps[4][128];
    __shared__ float pooled[128];
    __shared__ float xroot[312];
    __shared__ float red[256];

    int r0 = g_root[b], r1 = g_root[b + 1];
    float s = 0.f;
    for (int n = r0 + part; n < r1; n += 4) s += h[n * 128 + tt];
    ps[part][tt] = s;
    for (int k = t; k < IN_DIM; k += 512) xroot[k] = x[(long)r0 * IN_DIM + k];
    __syncthreads();
    if (part == 0)
        pooled[tt] = (ps[0][tt] + ps[1][tt] + ps[2][tt] + ps[3][tt]) / (float)(r1 - r0);
    __syncthreads();

    if (t < 128) {
        float accg = br[t];
        #pragma unroll 4
        for (int k = 0; k < 128; k++) accg = fmaf(pooled[k], Wr[k * 128 + t], accg);
        red[t] = fmaxf(accg, 0.f) * Wc[t];
    } else if (t < 256) {
        int j = t - 128;
        float accn = bn[j];
        for (int k = 0; k < IN_DIM; k++) accn = fmaf(xroot[k], Wn[k * 128 + j], accn);
        red[t] = fmaxf(accn, 0.f) * Wc[128 + j];
    }
    __syncthreads();
    for (int o = 128; o; o >>= 1) {
        if (t < o) red[t] += red[t + o];
        __syncthreads();
    }
    if (t == 0) out[b] = 1.f / (1.f + expf(-(red[0] + bc[0])));
}

// ---------------- launch ----------------
extern "C" void kernel_launch(void* const* d_in, const int* in_sizes, int n_in,
                              void* d_out, int out_size) {
    const float* x   = (const float*)d_in[0];
    const float* W0  = (const float*)d_in[1];
    const float* as0 = (const float*)d_in[2];
    const float* ad0 = (const float*)d_in[3];
    const float* b0  = (const float*)d_in[4];
    const float* W1  = (const float*)d_in[5];
    const float* as1 = (const float*)d_in[6];
    const float* ad1 = (const float*)d_in[7];
    const float* b1  = (const float*)d_in[8];
    const float* Wn  = (const float*)d_in[9];
    const float* bn  = (const float*)d_in[10];
    const float* Wr  = (const float*)d_in[11];
    const float* br  = (const float*)d_in[12];
    const float* Wc  = (const float*)d_in[13];
    const float* bc  = (const float*)d_in[14];
    const int*   ei  = (const int*)d_in[15];
    const int*   batch = (const int*)d_in[16];
    float* out = (float*)d_out;

    const int* src = ei;
    const int* dst = ei + EE;

    void *p_xwh, *p_h, *p_deg, *p_cur;
    cudaGetSymbolAddress(&p_xwh, g_xwh);
    cudaGetSymbolAddress(&p_h, g_h);
    cudaGetSymbolAddress(&p_deg, g_deg);
    cudaGetSymbolAddress(&p_cur, g_cursor);
    __half* xwh = (__half*)p_xwh;
    float* hbuf = (float*)p_h;

    // one-time setup: side stream, fork/join events, gemm smem opt-in
    static cudaStream_t s1 = nullptr;
    static cudaEvent_t evFork = nullptr, evJoin = nullptr;
    if (s1 == nullptr) {
        cudaStreamCreateWithFlags(&s1, cudaStreamNonBlocking);
        cudaEventCreateWithFlags(&evFork, cudaEventDisableTiming);
        cudaEventCreateWithFlags(&evJoin, cudaEventDisableTiming);
        cudaFuncSetAttribute(gemm_tf32, cudaFuncAttributeMaxDynamicSharedMemorySize,
                             GEMM_SMEM_BYTES);
    }

    // fork: CSR build on s1 runs concurrently with GEMM0 on s0
    cudaEventRecord(evFork, 0);
    cudaStreamWaitEvent(s1, evFork, 0);

    cudaMemsetAsync(p_deg, 0, NN * sizeof(int), s1);
    cudaMemsetAsync(p_cur, 0, NN * sizeof(int), s1);
    count_kernel<<<(EE / 4 + 255) / 256, 256, 0, s1>>>(dst);
    scan_kernel<<<1, 1024, 0, s1>>>(batch);
    fill_kernel<<<(EE / 4 + 255) / 256, 256, 0, s1>>>(src, dst);
    cudaEventRecord(evJoin, s1);

    // s0: GEMM0 starts immediately (raw weights, no prep kernels at all)
    gemm_tf32<<<(NN + BM - 1) / BM, 256, GEMM_SMEM_BYTES>>>(
        x, W0, xwh, as0, ad0, NN, IN_DIM, KP0);

    // join: aggregation needs both CSR and GEMM0
    cudaStreamWaitEvent(0, evJoin, 0);

    aggregate_kernel<<<(NN + 7) / 8, 256>>>(xwh, b0, hbuf);

    // GAT layer 1
    gemm_tf32<<<(NN + BM - 1) / BM, 256, GEMM_SMEM_BYTES>>>(
        hbuf, W1, xwh, as1, ad1, NN, 128, 128);
    aggregate_kernel<<<(NN + 7) / 8, 256>>>(xwh, b1, hbuf);

    // fused pooling + readout + news + concat + sigmoid
    pool_head_kernel<<<BB, 512>>>(hbuf, x, Wr, br, Wn, bn, Wc, bc, out);
}

// round 17
// speedup vs baseline: 1.2925x; 1.2925x over previous
#include <cuda_runtime.h>
#include <cuda_fp16.h>
#include <stdint.h>
#include <math.h>

// Problem constants (fixed shapes for this dataset)
#define NN 50000
#define EE 800000
#define BB 128
#define IN_DIM 310
#define KP0 320      // IN_DIM padded to multiple of 32
#define HD 128       // 2 heads x 64
#define NH 2

// ---------------- scratch (static device globals; no allocation) ----------------
__device__ __align__(16) __half g_Ax[NN * KP0];      // padded fp16 x (GEMM0 A)
__device__ __align__(16) __half g_Ah[NN * HD];       // fp16 copy of h (GEMM1 A)
__device__ __align__(16) __half g_Bh0[KP0 * 128];    // fp16 W0 (padded)
__device__ __align__(16) __half g_Bh1[128 * 128];    // fp16 W1
__device__ __align__(16) __half g_xwh[NN * HD];      // GEMM output fp16 (for gather)
__device__ __align__(16) float g_h[NN * HD];         // aggregated layer output
__device__ __align__(8) float g_asrc[NN * NH];
__device__ __align__(8) float g_adst[NN * NH];
__device__ int   g_deg[NN];
__device__ int   g_cursor[NN];
__device__ int   g_rowptr[NN + 1];
__device__ int   g_csrsrc[EE];
__device__ int   g_root[BB + 1];

__device__ __forceinline__ float lrelu(float z) { return z > 0.f ? z : 0.2f * z; }

// ---------------- CSR build ----------------
__global__ void count_kernel(const int* __restrict__ dst) {
    int i = blockIdx.x * blockDim.x + threadIdx.x;
    if (i < EE / 4) {
        int4 d = reinterpret_cast<const int4*>(dst)[i];
        atomicAdd(&g_deg[d.x], 1);
        atomicAdd(&g_deg[d.y], 1);
        atomicAdd(&g_deg[d.z], 1);
        atomicAdd(&g_deg[d.w], 1);
    }
}

__global__ void scan_kernel(const int* __restrict__ batch) {
    const int CH = (NN + 1023) / 1024;     // 49
    __shared__ int ws[32];
    int t = threadIdx.x, lane = t & 31, wid = t >> 5;

    if (t <= BB) {
        if (t == BB) g_root[BB] = NN;
        else {
            int lo = 0, hi = NN;
            while (lo < hi) {
                int mid = (lo + hi) >> 1;
                if (batch[mid] < t) lo = mid + 1; else hi = mid;
            }
            g_root[t] = lo;
        }
    }

    int lo = t * CH, hi = min(lo + CH, NN);
    if (lo > NN) lo = NN;
    if (hi < lo) hi = lo;
    int sum = 0;
    for (int i = lo; i < hi; i++) sum += g_deg[i];
    int x = sum;
    #pragma unroll
    for (int o = 1; o < 32; o <<= 1) {
        int y = __shfl_up_sync(0xffffffffu, x, o);
        if (lane >= o) x += y;
    }
    if (lane == 31) ws[wid] = x;
    __syncthreads();
    if (wid == 0) {
        int w = ws[lane];
        #pragma unroll
        for (int o = 1; o < 32; o <<= 1) {
            int y = __shfl_up_sync(0xffffffffu, w, o);
            if (lane >= o) w += y;
        }
        ws[lane] = w;
    }
    __syncthreads();
    int run = x - sum + (wid ? ws[wid - 1] : 0);
    for (int i = lo; i < hi; i++) { g_rowptr[i] = run; run += g_deg[i]; }
    if (t == 1023) g_rowptr[NN] = run;
}

__global__ void fill_kernel(const int* __restrict__ src, const int* __restrict__ dst) {
    int i = blockIdx.x * blockDim.x + threadIdx.x;
    if (i < EE / 4) {
        int4 s4 = reinterpret_cast<const int4*>(src)[i];
        int4 d4 = reinterpret_cast<const int4*>(dst)[i];
        int p0 = g_rowptr[d4.x] + atomicAdd(&g_cursor[d4.x], 1);
        int p1 = g_rowptr[d4.y] + atomicAdd(&g_cursor[d4.y], 1);
        int p2 = g_rowptr[d4.z] + atomicAdd(&g_cursor[d4.z], 1);
        int p3 = g_rowptr[d4.w] + atomicAdd(&g_cursor[d4.w], 1);
        g_csrsrc[p0] = s4.x;
        g_csrsrc[p1] = s4.y;
        g_csrsrc[p2] = s4.z;
        g_csrsrc[p3] = s4.w;
    }
}

// ---------------- prep: x fp32 -> padded fp16 A; W fp32 -> padded fp16 B -------
__global__ void padx_kernel(const float* __restrict__ x, __half* __restrict__ Ax) {
    long i = (long)blockIdx.x * blockDim.x + threadIdx.x;   // NN*160 half2 slots
    if (i >= (long)NN * (KP0 / 2)) return;
    int row = (int)(i / (KP0 / 2));
    int c2 = (int)(i % (KP0 / 2)) * 2;
    float2 v = make_float2(0.f, 0.f);
    if (c2 < IN_DIM) v = *reinterpret_cast<const float2*>(x + (long)row * IN_DIM + c2);
    *reinterpret_cast<__half2*>(Ax + (long)row * KP0 + c2) = __floats2half2_rn(v.x, v.y);
}

__global__ void convW_kernel(const float* __restrict__ W, __half* __restrict__ out,
                             int K, int Kp) {
    int i = blockIdx.x * blockDim.x + threadIdx.x;
    if (i >= Kp * 128) return;
    int k = i >> 7;
    out[i] = __float2half((k < K) ? W[i] : 0.f);
}

// ---------------- fp16 tensor-core GEMM: 128x128 tile, 8 warps, ldmatrix -------
// m16n8k16 f16 MMA (the fast legacy HMMA path on sm_103a). A,B pre-converted
// fp16 (RN, 2^-11 — same error class as the verified tf32-trunc run at 1.79e-4).
#define LDMX4(R, addr) \
    asm volatile("ldmatrix.sync.aligned.m8n8.x4.shared.b16 {%0,%1,%2,%3}, [%4];" \
        : "=r"((R)[0]), "=r"((R)[1]), "=r"((R)[2]), "=r"((R)[3]) : "r"(addr))
#define LDMX4T(r0, r1, r2, r3, addr) \
    asm volatile("ldmatrix.sync.aligned.m8n8.x4.trans.shared.b16 {%0,%1,%2,%3}, [%4];" \
        : "=r"(r0), "=r"(r1), "=r"(r2), "=r"(r3) : "r"(addr))
#define MMA16816F(Cr, Ar, B0, B1) \
    asm volatile("mma.sync.aligned.m16n8k16.row.col.f32.f16.f16.f32 " \
        "{%0,%1,%2,%3},{%4,%5,%6,%7},{%8,%9},{%0,%1,%2,%3};" \
        : "+f"((Cr)[0]), "+f"((Cr)[1]), "+f"((Cr)[2]), "+f"((Cr)[3]) \
        : "r"((Ar)[0]), "r"((Ar)[1]), "r"((Ar)[2]), "r"((Ar)[3]), "r"(B0), "r"(B1))
#define CP16P(dst, src, bytes) \
    asm volatile("cp.async.cg.shared.global [%0], [%1], 16, %2;" \
        :: "r"(dst), "l"(src), "r"(bytes))
#define CP_COMMIT() asm volatile("cp.async.commit_group;")
#define CP_WAIT(n)  asm volatile("cp.async.wait_group %0;" :: "n"(n))

#define SAH_STRIDE 40    // halves per A row (64B data + 16B pad)
#define SBH_STRIDE 136   // halves per B row (256B data + 16B pad)
#define SAH_ELEMS (128 * SAH_STRIDE)   // 5120
#define SBH_ELEMS (32 * SBH_STRIDE)    // 4352
#define GEMM_SMEM_BYTES ((2 * SAH_ELEMS + 2 * SBH_ELEMS) * 2)

__global__ __launch_bounds__(256) void gemm_fp16(
    const __half* __restrict__ A, const __half* __restrict__ Bh,
    __half* __restrict__ Ch,
    const float* __restrict__ aS, const float* __restrict__ aD,
    int M, int lda)
{
    extern __shared__ __half hsm[];
    __half* sA = hsm;                        // [2][128][40]
    __half* sB = hsm + 2 * SAH_ELEMS;        // [2][32][136]
    __shared__ float2 sal[128][4];           // per-(row, wn) (asrc, adst) partials

    int tid = threadIdx.x;
    int lane = tid & 31, warp = tid >> 5;
    int wm = warp >> 2, wn = warp & 3;   // 2 x 4 warps; warp tile 64 x 32
    int row0 = blockIdx.x * 128;
    int lm = lane >> 3, lr = lane & 7;   // ldmatrix addressing
    int gq = lane >> 2, tq = lane & 3;   // epilogue addressing

    float acc[4][4][4];
    #pragma unroll
    for (int a = 0; a < 4; a++)
        #pragma unroll
        for (int b = 0; b < 4; b++)
            #pragma unroll
            for (int c = 0; c < 4; c++) acc[a][b][c] = 0.f;

    unsigned sA_base = (unsigned)__cvta_generic_to_shared(sA);
    unsigned sB_base = (unsigned)__cvta_generic_to_shared(sB);
    int T = lda / 32;

    // async tile loader: 16B chunks everywhere (fp16 data, aligned buffers)
    auto issue = [&](int t, int buf) {
        int kt = t * 32;
        // A tile: 128 rows x 32 halves = 512 chunks; thread gets 2
        #pragma unroll
        for (int q = 0; q < 2; q++) {
            int ch = tid * 2 + q;
            int r = ch >> 2, c8 = (ch & 3) * 8;
            int gm = row0 + r;
            int bytes = (gm < M) ? 16 : 0;
            unsigned ds = sA_base + (unsigned)((buf * SAH_ELEMS + r * SAH_STRIDE + c8) * 2);
            const __half* srcp = A + (long)gm * lda + kt + c8;
            CP16P(ds, srcp, bytes);
        }
        // B tile: 32 rows x 128 halves = 512 chunks; thread gets 2 (Bh pre-padded)
        #pragma unroll
        for (int q = 0; q < 2; q++) {
            int ch = tid * 2 + q;
            int r = ch >> 4, c8 = (ch & 15) * 8;
            unsigned ds = sB_base + (unsigned)((buf * SBH_ELEMS + r * SBH_STRIDE + c8) * 2);
            const __half* srcp = Bh + (long)(kt + r) * 128 + c8;
            CP16P(ds, srcp, 16);
        }
    };

    issue(0, 0);
    CP_COMMIT();

    for (int t = 0; t < T; t++) {
        int buf = t & 1;
        if (t + 1 < T) {
            issue(t + 1, (t + 1) & 1);
            CP_COMMIT();
            CP_WAIT(1);
        } else {
            CP_WAIT(0);
        }
        __syncthreads();

        const __half* cA = sA + buf * SAH_ELEMS;
        const __half* cB = sB + buf * SBH_ELEMS;
        #pragma unroll
        for (int k16 = 0; k16 < 2; k16++) {
            unsigned int af[4][4], bf[4][2];
            #pragma unroll
            for (int mi = 0; mi < 4; mi++) {
                int rr = wm * 64 + mi * 16 + (lm & 1) * 8 + lr;
                int cc = k16 * 16 + (lm >> 1) * 8;
                unsigned ad = (unsigned)__cvta_generic_to_shared(&cA[rr * SAH_STRIDE + cc]);
                LDMX4(af[mi], ad);
            }
            #pragma unroll
            for (int np = 0; np < 2; np++) {
                int br = k16 * 16 + (lm & 1) * 8 + lr;
                int bc = wn * 32 + np * 16 + (lm >> 1) * 8;
                unsigned ad = (unsigned)__cvta_generic_to_shared(&cB[br * SBH_STRIDE + bc]);
                LDMX4T(bf[2 * np][0], bf[2 * np][1], bf[2 * np + 1][0], bf[2 * np + 1][1], ad);
            }
            #pragma unroll
            for (int mi = 0; mi < 4; mi++)
                #pragma unroll
                for (int nb = 0; nb < 4; nb++)
                    MMA16816F(acc[mi][nb], af[mi], bf[nb][0], bf[nb][1]);
        }
        __syncthreads();
    }

    // epilogue: fp16 store + alpha partials (shfl-reduced over tq, smem-combined)
    #pragma unroll
    for (int mi = 0; mi < 4; mi++) {
        int rb = row0 + wm * 64 + mi * 16 + gq;
        float s_lo = 0.f, s_hi = 0.f, d_lo = 0.f, d_hi = 0.f;
        #pragma unroll
        for (int nb = 0; nb < 4; nb++) {
            int cc = wn * 32 + nb * 8 + tq * 2;
            float as0 = aS[cc], as1 = aS[cc + 1];
            float ad0 = aD[cc], ad1 = aD[cc + 1];
            s_lo += acc[mi][nb][0] * as0 + acc[mi][nb][1] * as1;
            d_lo += acc[mi][nb][0] * ad0 + acc[mi][nb][1] * ad1;
            s_hi += acc[mi][nb][2] * as0 + acc[mi][nb][3] * as1;
            d_hi += acc[mi][nb][2] * ad0 + acc[mi][nb][3] * ad1;
            if (rb < M)
                *reinterpret_cast<__half2*>(&Ch[(long)rb * 128 + cc]) =
                    __floats2half2_rn(acc[mi][nb][0], acc[mi][nb][1]);
            if (rb + 8 < M)
                *reinterpret_cast<__half2*>(&Ch[(long)(rb + 8) * 128 + cc]) =
                    __floats2half2_rn(acc[mi][nb][2], acc[mi][nb][3]);
        }
        #pragma unroll
        for (int o = 1; o < 4; o <<= 1) {
            s_lo += __shfl_down_sync(0xffffffffu, s_lo, o, 4);
            d_lo += __shfl_down_sync(0xffffffffu, d_lo, o, 4);
            s_hi += __shfl_down_sync(0xffffffffu, s_hi, o, 4);
            d_hi += __shfl_down_sync(0xffffffffu, d_hi, o, 4);
        }
        if (tq == 0) {
            int rl = wm * 64 + mi * 16 + gq;
            sal[rl][wn] = make_float2(s_lo, d_lo);
            sal[rl + 8][wn] = make_float2(s_hi, d_hi);
        }
    }
    __syncthreads();
    {
        int row = tid >> 1, head = tid & 1;
        float2 a = sal[row][2 * head];
        float2 b = sal[row][2 * head + 1];
        int gr = row0 + row;
        if (gr < M) {
            g_asrc[2 * gr + head] = a.x + b.x;
            g_adst[2 * gr + head] = a.y + b.y;
        }
    }
}

// ---------------- GAT aggregation: warp per dst node, SINGLE PASS ----------------
// Writes fp32 h (for pooling) AND an fp16 copy (A of the next GEMM).
__global__ void aggregate_kernel(const __half* __restrict__ xh,
                                 const float* __restrict__ bias,
                                 float* __restrict__ out,
                                 __half* __restrict__ outh) {
    int gw = (blockIdx.x * blockDim.x + threadIdx.x) >> 5;
    int lane = threadIdx.x & 31;
    if (gw >= NN) return;
    int i = gw;
    int head = lane >> 4;
    float2 adp = *reinterpret_cast<const float2*>(&g_adst[2 * i]);
    float2 asp = *reinterpret_cast<const float2*>(&g_asrc[2 * i]);
    float ad0 = adp.x, ad1 = adp.y;
    float eSelf = head ? lrelu(asp.y + ad1) : lrelu(asp.x + ad0);
    int r0 = g_rowptr[i], r1 = g_rowptr[i + 1];

    float wself = __expf(eSelf);
    float den = wself;
    float4 acc;
    {
        uint2 raw = *reinterpret_cast<const uint2*>(&xh[(long)i * HD + lane * 4]);
        __half2 p0 = *reinterpret_cast<__half2*>(&raw.x);
        __half2 p1 = *reinterpret_cast<__half2*>(&raw.y);
        float2 f0 = __half22float2(p0);
        float2 f1 = __half22float2(p1);
        acc = make_float4(wself * f0.x, wself * f0.y, wself * f1.x, wself * f1.y);
    }

    for (int jb = r0; jb < r1; jb += 32) {
        int j = jb + lane;
        int s = 0; unsigned epk = 0;
        if (j < r1) {
            s = g_csrsrc[j];
            float2 a = *reinterpret_cast<const float2*>(&g_asrc[2 * s]);
            __half2 eh = __floats2half2_rn(lrelu(a.x + ad0), lrelu(a.y + ad1));
            epk = *reinterpret_cast<unsigned*>(&eh);
        }
        int cnt = min(32, r1 - jb);
        for (int k = 0; k < cnt; k++) {
            int      sk = __shfl_sync(0xffffffffu, s, k);
            unsigned ek = __shfl_sync(0xffffffffu, epk, k);
            __half2 ev = *reinterpret_cast<__half2*>(&ek);
            float e = head ? __high2float(ev) : __low2float(ev);
            float w = __expf(e);
            den += w;
            uint2 raw = *reinterpret_cast<const uint2*>(&xh[(long)sk * HD + lane * 4]);
            __half2 p0 = *reinterpret_cast<__half2*>(&raw.x);
            __half2 p1 = *reinterpret_cast<__half2*>(&raw.y);
            float2 f0 = __half22float2(p0);
            float2 f1 = __half22float2(p1);
            acc.x = fmaf(w, f0.x, acc.x);
            acc.y = fmaf(w, f0.y, acc.y);
            acc.z = fmaf(w, f1.x, acc.z);
            acc.w = fmaf(w, f1.y, acc.w);
        }
    }

    float inv = 1.f / (den + 1e-16f);
    float4 b = *reinterpret_cast<const float4*>(&bias[lane * 4]);
    float4 o;
    o.x = fmaxf(fmaf(acc.x, inv, b.x), 0.f);
    o.y = fmaxf(fmaf(acc.y, inv, b.y), 0.f);
    o.z = fmaxf(fmaf(acc.z, inv, b.z), 0.f);
    o.w = fmaxf(fmaf(acc.w, inv, b.w), 0.f);
    *reinterpret_cast<float4*>(&out[i * HD + lane * 4]) = o;
    uint2 ph;
    __half2 h0 = __floats2half2_rn(o.x, o.y);
    __half2 h1 = __floats2half2_rn(o.z, o.w);
    ph.x = *reinterpret_cast<unsigned*>(&h0);
    ph.y = *reinterpret_cast<unsigned*>(&h1);
    *reinterpret_cast<uint2*>(&outh[(long)i * HD + lane * 4]) = ph;
}

// ---------------- fused mean-pool + readout + news + concat + sigmoid ----------------
__global__ __launch_bounds__(512) void pool_head_kernel(
    const float* __restrict__ h, const float* __restrict__ x,
    const float* __restrict__ Wr, const float* __restrict__ br,
    const float* __restrict__ Wn, const float* __restrict__ bn,
    const float* __restrict__ Wc, const float* __restrict__ bc,
    float* __restrict__ out) {
    int b = blockIdx.x;
    int t = threadIdx.x;                    // 512
    int tt = t & 127, part = t >> 7;
    __shared__ float ps[4][128];
    __shared__ float pooled[128];
    __shared__ float xroot[312];
    __shared__ float red[256];

    int r0 = g_root[b], r1 = g_root[b + 1];
    float s = 0.f;
    for (int n = r0 + part; n < r1; n += 4) s += h[n * 128 + tt];
    ps[part][tt] = s;
    for (int k = t; k < IN_DIM; k += 512) xroot[k] = x[(long)r0 * IN_DIM + k];
    __syncthreads();
    if (part == 0)
        pooled[tt] = (ps[0][tt] + ps[1][tt] + ps[2][tt] + ps[3][tt]) / (float)(r1 - r0);
    __syncthreads();

    if (t < 128) {
        float accg = br[t];
        #pragma unroll 4
        for (int k = 0; k < 128; k++) accg = fmaf(pooled[k], Wr[k * 128 + t], accg);
        red[t] = fmaxf(accg, 0.f) * Wc[t];
    } else if (t < 256) {
        int j = t - 128;
        float accn = bn[j];
        for (int k = 0; k < IN_DIM; k++) accn = fmaf(xroot[k], Wn[k * 128 + j], accn);
        red[t] = fmaxf(accn, 0.f) * Wc[128 + j];
    }
    __syncthreads();
    for (int o = 128; o; o >>= 1) {
        if (t < o) red[t] += red[t + o];
        __syncthreads();
    }
    if (t == 0) out[b] = 1.f / (1.f + expf(-(red[0] + bc[0])));
}

// ---------------- launch ----------------
extern "C" void kernel_launch(void* const* d_in, const int* in_sizes, int n_in,
                              void* d_out, int out_size) {
    const float* x   = (const float*)d_in[0];
    const float* W0  = (const float*)d_in[1];
    const float* as0 = (const float*)d_in[2];
    const float* ad0 = (const float*)d_in[3];
    const float* b0  = (const float*)d_in[4];
    const float* W1  = (const float*)d_in[5];
    const float* as1 = (const float*)d_in[6];
    const float* ad1 = (const float*)d_in[7];
    const float* b1  = (const float*)d_in[8];
    const float* Wn  = (const float*)d_in[9];
    const float* bn  = (const float*)d_in[10];
    const float* Wr  = (const float*)d_in[11];
    const float* br  = (const float*)d_in[12];
    const float* Wc  = (const float*)d_in[13];
    const float* bc  = (const float*)d_in[14];
    const int*   ei  = (const int*)d_in[15];
    const int*   batch = (const int*)d_in[16];
    float* out = (float*)d_out;

    const int* src = ei;
    const int* dst = ei + EE;

    void *p_Ax, *p_Ah, *p_Bh0, *p_Bh1, *p_xwh, *p_h, *p_deg, *p_cur;
    cudaGetSymbolAddress(&p_Ax, g_Ax);
    cudaGetSymbolAddress(&p_Ah, g_Ah);
    cudaGetSymbolAddress(&p_Bh0, g_Bh0);
    cudaGetSymbolAddress(&p_Bh1, g_Bh1);
    cudaGetSymbolAddress(&p_xwh, g_xwh);
    cudaGetSymbolAddress(&p_h, g_h);
    cudaGetSymbolAddress(&p_deg, g_deg);
    cudaGetSymbolAddress(&p_cur, g_cursor);
    __half* Ax = (__half*)p_Ax;
    __half* Ah = (__half*)p_Ah;
    __half* xwh = (__half*)p_xwh;
    float* hbuf = (float*)p_h;

    // one-time setup: side stream, fork/join events, gemm smem opt-in
    static cudaStream_t s1 = nullptr;
    static cudaEvent_t evFork = nullptr, evJoin = nullptr;
    if (s1 == nullptr) {
        cudaStreamCreateWithFlags(&s1, cudaStreamNonBlocking);
        cudaEventCreateWithFlags(&evFork, cudaEventDisableTiming);
        cudaEventCreateWithFlags(&evJoin, cudaEventDisableTiming);
        cudaFuncSetAttribute(gemm_fp16, cudaFuncAttributeMaxDynamicSharedMemorySize,
                             GEMM_SMEM_BYTES);
    }

    // fork: CSR build (+ convW1) on s1 runs concurrently with prep+GEMM0 on s0
    cudaEventRecord(evFork, 0);
    cudaStreamWaitEvent(s1, evFork, 0);

    cudaMemsetAsync(p_deg, 0, NN * sizeof(int), s1);
    cudaMemsetAsync(p_cur, 0, NN * sizeof(int), s1);
    count_kernel<<<(EE / 4 + 255) / 256, 256, 0, s1>>>(dst);
    scan_kernel<<<1, 1024, 0, s1>>>(batch);
    fill_kernel<<<(EE / 4 + 255) / 256, 256, 0, s1>>>(src, dst);
    convW_kernel<<<(128 * 128 + 255) / 256, 256, 0, s1>>>(W1, (__half*)p_Bh1, 128, 128);
    cudaEventRecord(evJoin, s1);

    // s0: prep (padded fp16 x, fp16 W0) + GEMM0
    convW_kernel<<<(KP0 * 128 + 255) / 256, 256>>>(W0, (__half*)p_Bh0, IN_DIM, KP0);
    {
        long nh2 = (long)NN * (KP0 / 2);
        padx_kernel<<<(unsigned)((nh2 + 255) / 256), 256>>>(x, Ax);
    }
    gemm_fp16<<<(NN + 127) / 128, 256, GEMM_SMEM_BYTES>>>(
        Ax, (__half*)p_Bh0, xwh, as0, ad0, NN, KP0);

    // join: aggregation needs both CSR and GEMM0 (convW1 also done by here)
    cudaStreamWaitEvent(0, evJoin, 0);

    aggregate_kernel<<<(NN + 7) / 8, 256>>>(xwh, b0, hbuf, Ah);

    // GAT layer 1
    gemm_fp16<<<(NN + 127) / 128, 256, GEMM_SMEM_BYTES>>>(
        Ah, (__half*)p_Bh1, xwh, as1, ad1, NN, 128);
    aggregate_kernel<<<(NN + 7) / 8, 256>>>(xwh, b1, hbuf, Ah);

    // fused pooling + readout + news + concat + sigmoid
    pool_head_kernel<<<BB, 512>>>(hbuf, x, Wr, br, Wn, bn, Wc, bc, out);
}